// round 13
// baseline (speedup 1.0000x reference)
#include <cuda_runtime.h>
#include <math_constants.h>

// LIF_13984413516471  — B=128, S=128, H=128, K=8.
// s += x; spike = s > th[k]; out = spike ? s : 0; s -= out — serial (i,j,k).
// Output: outs[b][i][k][j], spikes[b][i][k][j].
//
// A : spec sim per chunk (one i-row, 1024 substeps) from s=0; smem-staged
//     coalesced output; metadata: spec end E, chunk sum S, and EXACT silence
//     bound M = max_j(p_j + c(x_j)), c(x) = max_m(m*x - th[m-1]): a linear
//     trajectory from s_in never spikes iff s_in <= -M (margin for FP drift).
// B1: warp/batch O(1)-per-chunk state walk (no x): cls0 s==0 exact;
//     cls1 silent jump; cls2 assume co-spike merge (s -> E).
// V : warp/chunk: cls1 zero-fill; cls2 dual resim from g_in, diff-patch,
//     early exit at co-spike; no merge -> bad flag + true end g_endv.
//     INVARIANT after V: memory of chunk c == outputs of trajectory from
//     g_in[c] (cls0 spec, cls1 zeros, cls2 g_in-trajectory).
// R : warp/batch repair: no-bad fast exit; off-chain silent -> zero-fill
//     (only if cls!=1) + O(1) jump; off-chain active -> dual resim vs the
//     g_in-trajectory w/ early exit; exact bitwise chain-return.

#define BB 128
#define SS 128
#define HH 128
#define KK 8
#define NCHUNK (BB * SS)          // 16384
#define CPW 16                    // chunks per warp in A
#define WPB 4                     // warps per block in A
#define QJ 8                      // j-steps per smem tile
#define NQ (HH / QJ)              // 16
#define CH_STRIDE (KK * QJ + 1)   // 65: lane stride ≡ 1 mod 32 (conflict-free)
#define MARGIN 0.01f

__device__ float g_E[NCHUNK];          // spec end state
__device__ float g_S[NCHUNK];          // chunk sum (per-j jumps)
__device__ float g_M[NCHUNK];          // exact linear-trajectory spike bound
__device__ float g_in[NCHUNK];         // B1 state entering chunk
__device__ float g_endv[NCHUNK];       // V: true end when not merged
__device__ unsigned char g_cls[NCHUNK];
__device__ unsigned char g_bad[NCHUNK];

// ---------------------------------------------------------------- kernel A
__global__ __launch_bounds__(128) void lif_spec_kernel(
    const float* __restrict__ x, const float* __restrict__ th,
    float* __restrict__ outs, float* __restrict__ spikes, int write_spikes)
{
    __shared__ float buf[WPB][CPW * CH_STRIDE];   // ≈ 16.6 KB

    const int w    = threadIdx.x >> 5;
    const int lane = threadIdx.x & 31;
    const int gw   = blockIdx.x * WPB + w;
    const int chunk0 = gw * CPW;

    float t[KK];
#pragma unroll
    for (int k = 0; k < KK; ++k) t[k] = __ldg(th + k);

    const bool active = lane < CPW;
    const int cl = active ? lane : 0;
    const float* __restrict__ xr = x + (size_t)(chunk0 + cl) * HH;
    float* bp = &buf[w][cl * CH_STRIDE];

    float s = 0.0f;
    float p = 0.0f;                  // per-j jumped prefix
    float Mp = -CUDART_INF_F;        // exact: max_j (p_j + c(x_j))

    for (int q = 0; q < NQ; ++q) {
        if (active) {
#pragma unroll
            for (int g = 0; g < QJ / 4; ++g) {
                float4 xv = *reinterpret_cast<const float4*>(xr + q * QJ + g * 4);
                float xa[4] = {xv.x, xv.y, xv.z, xv.w};
#pragma unroll
                for (int jj = 0; jj < 4; ++jj) {
                    float xx = xa[jj];
                    int j = g * 4 + jj;
                    // exact per-j spike reach: c = max_m(m*x - th[m-1])
                    float c = fmaf(1.0f, xx, -t[0]);
#pragma unroll
                    for (int k = 1; k < KK; ++k)
                        c = fmaxf(c, fmaf((float)(k + 1), xx, -t[k]));
                    Mp = fmaxf(Mp, p + c);
                    p += 8.0f * xx;
#pragma unroll
                    for (int k = 0; k < KK; ++k) {
                        s += xx;
                        bool sp = s > t[k];
                        bp[k * QJ + j] = sp ? s : 0.0f;
                        s = sp ? 0.0f : s;
                    }
                }
            }
        }
        __syncwarp();
        {
            int jf = lane & 7;
            int ch = lane >> 3;                      // 0..3
#pragma unroll
            for (int cp = 0; cp < CPW / 4; ++cp) {
                int c = cp * 4 + ch;
                size_t gbase = (size_t)(chunk0 + c) * (KK * HH) + q * QJ + jf;
                const float* sbf = &buf[w][c * CH_STRIDE + jf];
#pragma unroll
                for (int k = 0; k < KK; ++k) {
                    float v = sbf[k * QJ];
                    outs[gbase + k * HH] = v;
                    if (write_spikes)
                        spikes[gbase + k * HH] = v > 0.0f ? 1.0f : 0.0f;
                }
            }
        }
        __syncwarp();
    }

    if (active) {
        g_E[chunk0 + lane] = s;
        g_S[chunk0 + lane] = p;
        g_M[chunk0 + lane] = Mp;
    }
}

// ---------------------------------------------------------------- kernel B1
__global__ __launch_bounds__(32) void lif_state_kernel()
{
    __shared__ float smM[SS], smS[SS], smE[SS];
    const int b = blockIdx.x, lane = threadIdx.x, base = b * SS;

#pragma unroll
    for (int r = 0; r < SS / 32; ++r) {
        int i = r * 32 + lane;
        smM[i] = g_M[base + i];
        smS[i] = g_S[base + i];
        smE[i] = g_E[base + i];
    }
    __syncwarp();
    if (lane != 0) return;

    float s = 0.0f;
    for (int i = 0; i < SS; ++i) {
        int c = base + i;
        g_in[c] = s;
        g_bad[c] = 0;
        if (s == 0.0f)                      { g_cls[c] = 0; s = smE[i]; }
        else if (s <= -(smM[i] + MARGIN))   { g_cls[c] = 1; s += smS[i]; }
        else                                { g_cls[c] = 2; s = smE[i]; }  // assume merge
    }
}

// --------------------------------------------------------- shared dual resim
// Resim trajectory-b (start sb) against trajectory-a (start sa == what the
// chunk's memory currently holds). Diff-patch; early exit at co-spike (both
// reset to exact 0 -> identical afterward; memory already correct beyond).
// Returns true if merged; otherwise *end_out = final sb.
__device__ __forceinline__ bool dual_patch(
    const float* __restrict__ xrow, const float* __restrict__ t,
    float sa, float sb, float* __restrict__ orow, float* __restrict__ srow,
    int write_spikes, float* end_out)
{
    const float4* __restrict__ xr4 = reinterpret_cast<const float4*>(xrow);
    float4 cur = xr4[0];
    for (int g = 0; g < HH / 4; ++g) {
        float4 nxt = (g + 1 < HH / 4) ? xr4[g + 1] : cur;
        float xa[4] = {cur.x, cur.y, cur.z, cur.w};
#pragma unroll
        for (int jj = 0; jj < 4; ++jj) {
            float xx = xa[jj];
            int j = g * 4 + jj;
#pragma unroll
            for (int k = 0; k < KK; ++k) {
                sa += xx; sb += xx;
                bool spa = sa > t[k];
                bool spb = sb > t[k];
                int idx = k * HH + j;
                if (spa && spb) { orow[idx] = sb; return true; }
                float ot = spb ? sb : 0.0f;
                float os = spa ? sa : 0.0f;
                if (ot != os) orow[idx] = ot;
                if (write_spikes && (spa != spb)) srow[idx] = spb ? 1.0f : 0.0f;
                sa = spa ? 0.0f : sa;
                sb = spb ? 0.0f : sb;
            }
        }
        cur = nxt;
    }
    *end_out = sb;
    return false;
}

// ---------------------------------------------------------------- kernel V
__global__ __launch_bounds__(256) void lif_verify_kernel(
    const float* __restrict__ x, const float* __restrict__ th,
    float* __restrict__ outs, float* __restrict__ spikes, int write_spikes)
{
    int chunk = (blockIdx.x * blockDim.x + threadIdx.x) >> 5;
    int lane  = threadIdx.x & 31;
    if (chunk >= NCHUNK) return;

    unsigned char cls = g_cls[chunk];
    if (cls == 0) return;                       // spec outputs already exact

    float* orow = outs + (size_t)chunk * (KK * HH);
    float* srow = spikes + (size_t)chunk * (KK * HH);

    if (cls == 1) {                             // silent: zero-fill (coalesced)
        float4 z = make_float4(0.f, 0.f, 0.f, 0.f);
        float4* o4 = reinterpret_cast<float4*>(orow);
        float4* s4 = reinterpret_cast<float4*>(srow);
#pragma unroll
        for (int it = 0; it < (KK * HH / 4) / 32; ++it) {
            o4[it * 32 + lane] = z;
            if (write_spikes) s4[it * 32 + lane] = z;
        }
        return;
    }

    // cls == 2: dual resim from recorded s_in vs spec (memory = spec).
    float t[KK];
#pragma unroll
    for (int k = 0; k < KK; ++k) t[k] = __ldg(th + k);

    float endv;
    bool merged = dual_patch(x + (size_t)chunk * HH, t, 0.0f, g_in[chunk],
                             orow, srow, write_spikes, &endv);
    if (!merged && lane == 0) { g_endv[chunk] = endv; g_bad[chunk] = 1; }
}

// ---------------------------------------------------------------- kernel R
__global__ __launch_bounds__(32) void lif_repair_kernel(
    const float* __restrict__ x, const float* __restrict__ th,
    float* __restrict__ outs, float* __restrict__ spikes, int write_spikes)
{
    __shared__ float smIn[SS], smE[SS], smS[SS], smM[SS], smEndv[SS];
    __shared__ unsigned char smBad[SS], smCls[SS];

    const int b = blockIdx.x, lane = threadIdx.x, base = b * SS;

    // fast no-bad exit (4 flag bytes per lane)
    unsigned int word = reinterpret_cast<const unsigned int*>(g_bad + base)[lane];
    unsigned int ballot = __ballot_sync(0xFFFFFFFFu, word != 0u);
    if (!ballot) return;

    // cooperative metadata prefetch
#pragma unroll
    for (int r = 0; r < SS / 32; ++r) {
        int i = r * 32 + lane;
        smIn[i]   = g_in[base + i];
        smE[i]    = g_E[base + i];
        smS[i]    = g_S[base + i];
        smM[i]    = g_M[base + i];
        smEndv[i] = g_endv[base + i];
        smBad[i]  = g_bad[base + i];
        smCls[i]  = g_cls[base + i];
    }
    __syncwarp();

    float t[KK];
#pragma unroll
    for (int k = 0; k < KK; ++k) t[k] = __ldg(th + k);

    // first bad chunk: its s_in (B1 chain) was correct, V patch valid.
    int i = 0;
    while (i < SS && !smBad[i]) ++i;
    if (i >= SS) return;
    float s = smEndv[i];
    ++i;

    while (i < SS) {
        // exact bitwise chain-return test
        if (s == smIn[i]) {
            while (i < SS && !smBad[i]) ++i;   // on chain until next bad
            if (i >= SS) return;
            s = smEndv[i];          // its s_in was on-chain -> patch valid
            ++i;
            continue;
        }

        int c = base + i;
        float* orow = outs + (size_t)c * (KK * HH);
        float* srow = spikes + (size_t)c * (KK * HH);

        if (s <= -(smM[i] + MARGIN)) {
            // truly silent: outputs must be zero
            if (smCls[i] != 1) {     // memory not already zeros
                float4 z = make_float4(0.f, 0.f, 0.f, 0.f);
                float4* o4 = reinterpret_cast<float4*>(orow);
                float4* s4 = reinterpret_cast<float4*>(srow);
#pragma unroll
                for (int it = 0; it < (KK * HH / 4) / 32; ++it) {
                    o4[it * 32 + lane] = z;
                    if (write_spikes) s4[it * 32 + lane] = z;
                }
            }
            s += smS[i];
            ++i;
            continue;
        }

        // active off-chain: memory holds the g_in-trajectory (invariant).
        float endv;
        bool merged = dual_patch(x + (size_t)c * HH, t, smIn[i], s,
                                 orow, srow, write_spikes, &endv);
        if (merged) {
            // identical to the g_in-trajectory afterward -> its exact end:
            s = smBad[i] ? smEndv[i] : smE[i];
        } else {
            s = endv;
        }
        ++i;
    }
}

extern "C" void kernel_launch(void* const* d_in, const int* in_sizes, int n_in,
                              void* d_out, int out_size) {
    const float* x  = (const float*)d_in[0];   // (B, S, H) f32
    const float* th = (const float*)d_in[1];   // (K,) f32
    float* outs = (float*)d_out;

    const long long N = (long long)BB * SS * KK * HH;   // 16777216
    int write_spikes = ((long long)out_size >= 2 * N) ? 1 : 0;
    float* spikes = outs + N;

    lif_spec_kernel<<<NCHUNK / (CPW * WPB), WPB * 32>>>(x, th, outs, spikes,
                                                        write_spikes);
    lif_state_kernel<<<BB, 32>>>();
    lif_verify_kernel<<<(NCHUNK * 32) / 256, 256>>>(x, th, outs, spikes,
                                                    write_spikes);
    lif_repair_kernel<<<BB, 32>>>(x, th, outs, spikes, write_spikes);
}

// round 14
// speedup vs baseline: 1.1697x; 1.1697x over previous
#include <cuda_runtime.h>
#include <math_constants.h>

// LIF_13984413516471  — B=128, S=128, H=128, K=8.
// s += x; spike = s > th[k]; out = spike ? s : 0; s -= out — serial (i,j,k).
// Output: outs[b][i][k][j], spikes[b][i][k][j].
//
// A : spec sim per chunk (one i-row, 1024 substeps) from s=0; smem-staged
//     coalesced output (CPW16/QJ16 + STS.64 pairing); metadata: spec end E,
//     chunk sum S, EXACT silence bound M = max_j(p_j + c(x_j)),
//     c(x) = max_m(m*x - th[m-1]).
// B1: warp/batch O(1)-per-chunk state walk (no x): cls0 s==0 exact;
//     cls1 silent jump; cls2 assume co-spike merge (s -> E).
// V : warp/chunk: cls1 zero-fill; cls2 dual resim from g_in, diff-patch,
//     group-granular merge exit; no merge -> bad flag + true end g_endv.
//     INVARIANT after V: memory of chunk c == outputs of trajectory from
//     g_in[c].
// R : warp/batch repair: no-bad fast exit; off-chain silent -> zero-fill
//     (only if cls!=1) + O(1) jump; off-chain active -> dual resim vs the
//     g_in-trajectory; exact bitwise chain-return; L1 x-prefetch lookahead.

#define BB 128
#define SS 128
#define HH 128
#define KK 8
#define NCHUNK (BB * SS)          // 16384
#define CPW 16                    // chunks per warp in A
#define WPB 4                     // warps per block in A
#define QJ 16                     // j-steps per smem tile
#define NQ (HH / QJ)              // 8
#define CH_STRIDE 130             // floats; even (STS.64) + 16-lane conflict-free
#define MARGIN 0.01f

__device__ float g_E[NCHUNK];          // spec end state
__device__ float g_S[NCHUNK];          // chunk sum (per-j jumps)
__device__ float g_M[NCHUNK];          // exact linear-trajectory spike bound
__device__ float g_in[NCHUNK];         // B1 state entering chunk
__device__ float g_endv[NCHUNK];       // V: true end when not merged
__device__ unsigned char g_cls[NCHUNK];
__device__ unsigned char g_bad[NCHUNK];

// ---------------------------------------------------------------- kernel A
__global__ __launch_bounds__(128) void lif_spec_kernel(
    const float* __restrict__ x, const float* __restrict__ th,
    float* __restrict__ outs, float* __restrict__ spikes, int write_spikes)
{
    __shared__ float buf[WPB][CPW * CH_STRIDE];   // 4*2080*4 = 33.3 KB

    const int w    = threadIdx.x >> 5;
    const int lane = threadIdx.x & 31;
    const int gw   = blockIdx.x * WPB + w;
    const int chunk0 = gw * CPW;

    float t[KK];
#pragma unroll
    for (int k = 0; k < KK; ++k) t[k] = __ldg(th + k);

    const bool active = lane < CPW;
    const int cl = active ? lane : 0;
    const float* __restrict__ xr = x + (size_t)(chunk0 + cl) * HH;
    float* bp = &buf[w][cl * CH_STRIDE];

    float s = 0.0f;
    float p = 0.0f;                  // per-j jumped prefix
    float Mp = -CUDART_INF_F;        // exact: max_j (p_j + c(x_j))

    for (int q = 0; q < NQ; ++q) {
        if (active) {
#pragma unroll
            for (int g = 0; g < QJ / 4; ++g) {
                float4 xv = *reinterpret_cast<const float4*>(xr + q * QJ + g * 4);
                float xa[4] = {xv.x, xv.y, xv.z, xv.w};
                float o0[KK], o1[KK];
#pragma unroll
                for (int pr = 0; pr < 2; ++pr) {          // j-pairs
#pragma unroll
                    for (int jj = 0; jj < 2; ++jj) {
                        float xx = xa[pr * 2 + jj];
                        // exact per-j spike reach: c = max_m(m*x - th[m-1])
                        float c = fmaf(1.0f, xx, -t[0]);
#pragma unroll
                        for (int k = 1; k < KK; ++k)
                            c = fmaxf(c, fmaf((float)(k + 1), xx, -t[k]));
                        Mp = fmaxf(Mp, p + c);
                        p += 8.0f * xx;
                        float* ob = jj ? o1 : o0;
#pragma unroll
                        for (int k = 0; k < KK; ++k) {
                            s += xx;
                            bool sp = s > t[k];
                            ob[k] = sp ? s : 0.0f;
                            s = sp ? 0.0f : s;
                        }
                    }
                    int j0 = g * 4 + pr * 2;              // even
#pragma unroll
                    for (int k = 0; k < KK; ++k) {
                        float2 v2 = make_float2(o0[k], o1[k]);
                        *reinterpret_cast<float2*>(bp + k * QJ + j0) = v2;  // STS.64
                    }
                }
            }
        }
        __syncwarp();
        {
            int jf = lane & 15;
            int ch = lane >> 4;                      // 0..1
#pragma unroll
            for (int cp = 0; cp < CPW / 2; ++cp) {
                int c = cp * 2 + ch;
                size_t gbase = (size_t)(chunk0 + c) * (KK * HH) + q * QJ + jf;
                const float* sbf = &buf[w][c * CH_STRIDE + jf];
#pragma unroll
                for (int k = 0; k < KK; ++k) {
                    float v = sbf[k * QJ];
                    outs[gbase + k * HH] = v;
                    if (write_spikes)
                        spikes[gbase + k * HH] = v > 0.0f ? 1.0f : 0.0f;
                }
            }
        }
        __syncwarp();
    }

    if (active) {
        g_E[chunk0 + lane] = s;
        g_S[chunk0 + lane] = p;
        g_M[chunk0 + lane] = Mp;
    }
}

// ---------------------------------------------------------------- kernel B1
__global__ __launch_bounds__(32) void lif_state_kernel()
{
    __shared__ float smM[SS], smS[SS], smE[SS];
    const int b = blockIdx.x, lane = threadIdx.x, base = b * SS;

#pragma unroll
    for (int r = 0; r < SS / 32; ++r) {
        int i = r * 32 + lane;
        smM[i] = g_M[base + i];
        smS[i] = g_S[base + i];
        smE[i] = g_E[base + i];
    }
    __syncwarp();
    if (lane != 0) return;

    float s = 0.0f;
    for (int i = 0; i < SS; ++i) {
        int c = base + i;
        g_in[c] = s;
        g_bad[c] = 0;
        if (s == 0.0f)                      { g_cls[c] = 0; s = smE[i]; }
        else if (s <= -(smM[i] + MARGIN))   { g_cls[c] = 1; s += smS[i]; }
        else                                { g_cls[c] = 2; s = smE[i]; }  // assume merge
    }
}

// --------------------------------------------------------- shared dual resim
// Resim trajectory-b (start sb) vs trajectory-a (start sa == chunk memory).
// Diff-patch; after a co-spike both trajectories are bitwise-identical, so
// all further writes are no-ops — merge check once per 32 substeps is exact.
// Returns true if merged; otherwise *end_out = final sb.
__device__ __forceinline__ bool dual_patch(
    const float* __restrict__ xrow, const float* __restrict__ t,
    float sa, float sb, float* __restrict__ orow, float* __restrict__ srow,
    int write_spikes, float* end_out)
{
    const float4* __restrict__ xr4 = reinterpret_cast<const float4*>(xrow);
    float4 cur = xr4[0];
    for (int g = 0; g < HH / 4; ++g) {
        float4 nxt = (g + 1 < HH / 4) ? xr4[g + 1] : cur;
        float xa[4] = {cur.x, cur.y, cur.z, cur.w};
        bool co = false;
#pragma unroll
        for (int jj = 0; jj < 4; ++jj) {
            float xx = xa[jj];
            int j = g * 4 + jj;
#pragma unroll
            for (int k = 0; k < KK; ++k) {
                sa += xx; sb += xx;
                bool spa = sa > t[k];
                bool spb = sb > t[k];
                co = co || (spa && spb);
                int idx = k * HH + j;
                float ot = spb ? sb : 0.0f;
                float os = spa ? sa : 0.0f;
                if (ot != os) orow[idx] = ot;
                if (write_spikes && (spa != spb)) srow[idx] = spb ? 1.0f : 0.0f;
                sa = spa ? 0.0f : sa;
                sb = spb ? 0.0f : sb;
            }
        }
        if (co) return true;
        cur = nxt;
    }
    *end_out = sb;
    return false;
}

// ---------------------------------------------------------------- kernel V
__global__ __launch_bounds__(256) void lif_verify_kernel(
    const float* __restrict__ x, const float* __restrict__ th,
    float* __restrict__ outs, float* __restrict__ spikes, int write_spikes)
{
    int chunk = (blockIdx.x * blockDim.x + threadIdx.x) >> 5;
    int lane  = threadIdx.x & 31;
    if (chunk >= NCHUNK) return;

    unsigned char cls = g_cls[chunk];
    if (cls == 0) return;                       // spec outputs already exact

    float* orow = outs + (size_t)chunk * (KK * HH);
    float* srow = spikes + (size_t)chunk * (KK * HH);

    if (cls == 1) {                             // silent: zero-fill (coalesced)
        float4 z = make_float4(0.f, 0.f, 0.f, 0.f);
        float4* o4 = reinterpret_cast<float4*>(orow);
        float4* s4 = reinterpret_cast<float4*>(srow);
#pragma unroll
        for (int it = 0; it < (KK * HH / 4) / 32; ++it) {
            o4[it * 32 + lane] = z;
            if (write_spikes) s4[it * 32 + lane] = z;
        }
        return;
    }

    // cls == 2: dual resim from recorded s_in vs spec (memory = spec).
    float t[KK];
#pragma unroll
    for (int k = 0; k < KK; ++k) t[k] = __ldg(th + k);

    float endv;
    bool merged = dual_patch(x + (size_t)chunk * HH, t, 0.0f, g_in[chunk],
                             orow, srow, write_spikes, &endv);
    if (!merged && lane == 0) { g_endv[chunk] = endv; g_bad[chunk] = 1; }
}

// ---------------------------------------------------------------- kernel R
__global__ __launch_bounds__(32) void lif_repair_kernel(
    const float* __restrict__ x, const float* __restrict__ th,
    float* __restrict__ outs, float* __restrict__ spikes, int write_spikes)
{
    __shared__ float smIn[SS], smE[SS], smS[SS], smM[SS], smEndv[SS];
    __shared__ unsigned char smBad[SS], smCls[SS];

    const int b = blockIdx.x, lane = threadIdx.x, base = b * SS;

    // fast no-bad exit (4 flag bytes per lane)
    unsigned int word = reinterpret_cast<const unsigned int*>(g_bad + base)[lane];
    unsigned int ballot = __ballot_sync(0xFFFFFFFFu, word != 0u);
    if (!ballot) return;

    // cooperative metadata prefetch
#pragma unroll
    for (int r = 0; r < SS / 32; ++r) {
        int i = r * 32 + lane;
        smIn[i]   = g_in[base + i];
        smE[i]    = g_E[base + i];
        smS[i]    = g_S[base + i];
        smM[i]    = g_M[base + i];
        smEndv[i] = g_endv[base + i];
        smBad[i]  = g_bad[base + i];
        smCls[i]  = g_cls[base + i];
    }
    __syncwarp();

    float t[KK];
#pragma unroll
    for (int k = 0; k < KK; ++k) t[k] = __ldg(th + k);

    // first bad chunk: its s_in (B1 chain) was correct, V patch valid.
    int i = 0;
    while (i < SS && !smBad[i]) ++i;
    if (i >= SS) return;
    float s = smEndv[i];
    ++i;

    while (i < SS) {
        // exact bitwise chain-return test
        if (s == smIn[i]) {
            while (i < SS && !smBad[i]) ++i;   // on chain until next bad
            if (i >= SS) return;
            s = smEndv[i];          // its s_in was on-chain -> patch valid
            ++i;
            continue;
        }

        // off-chain: prefetch x row two chunks ahead into L1 (hide latency)
        if (i + 2 < SS && lane < 16)
            asm volatile("prefetch.global.L1 [%0];"
                         :: "l"(x + (size_t)(base + i + 2) * HH + lane * 8));

        int c = base + i;
        float* orow = outs + (size_t)c * (KK * HH);
        float* srow = spikes + (size_t)c * (KK * HH);

        if (s <= -(smM[i] + MARGIN)) {
            // truly silent: outputs must be zero
            if (smCls[i] != 1) {     // memory not already zeros
                float4 z = make_float4(0.f, 0.f, 0.f, 0.f);
                float4* o4 = reinterpret_cast<float4*>(orow);
                float4* s4 = reinterpret_cast<float4*>(srow);
#pragma unroll
                for (int it = 0; it < (KK * HH / 4) / 32; ++it) {
                    o4[it * 32 + lane] = z;
                    if (write_spikes) s4[it * 32 + lane] = z;
                }
            }
            s += smS[i];
            ++i;
            continue;
        }

        // active off-chain: memory holds the g_in-trajectory (invariant).
        float endv;
        bool merged = dual_patch(x + (size_t)c * HH, t, smIn[i], s,
                                 orow, srow, write_spikes, &endv);
        if (merged) {
            // identical to the g_in-trajectory afterward -> its exact end:
            s = smBad[i] ? smEndv[i] : smE[i];
        } else {
            s = endv;
        }
        ++i;
    }
}

extern "C" void kernel_launch(void* const* d_in, const int* in_sizes, int n_in,
                              void* d_out, int out_size) {
    const float* x  = (const float*)d_in[0];   // (B, S, H) f32
    const float* th = (const float*)d_in[1];   // (K,) f32
    float* outs = (float*)d_out;

    const long long N = (long long)BB * SS * KK * HH;   // 16777216
    int write_spikes = ((long long)out_size >= 2 * N) ? 1 : 0;
    float* spikes = outs + N;

    lif_spec_kernel<<<NCHUNK / (CPW * WPB), WPB * 32>>>(x, th, outs, spikes,
                                                        write_spikes);
    lif_state_kernel<<<BB, 32>>>();
    lif_verify_kernel<<<(NCHUNK * 32) / 256, 256>>>(x, th, outs, spikes,
                                                    write_spikes);
    lif_repair_kernel<<<BB, 32>>>(x, th, outs, spikes, write_spikes);
}

// round 15
// speedup vs baseline: 1.9110x; 1.6338x over previous
#include <cuda_runtime.h>
#include <math_constants.h>

// LIF_13984413516471  — B=128, S=128, H=128, K=8.
// s += x; spike = s > th[k]; out = spike ? s : 0; s -= out — serial (i,j,k).
// Output: outs[b][i][k][j], spikes[b][i][k][j].
//
// Mt : metadata-only sim per chunk (thread/chunk, no output writes):
//      spec end E, chunk sum S, EXACT silence bound M = max_j(p_j + c(x_j)),
//      c(x) = max_m(m*x - th[m-1]).
// B1 : warp/batch O(1)-per-chunk state walk (no x): cls0 s==0 exact;
//      cls1 silent jump; cls2 assume co-spike merge (s -> E).
// W  : single classified writer (A-style smem staging, CPW16/QJ16):
//      lane sims ONE trajectory from g_in[c] (cls1 -> sentinel -1e30 => all
//      outputs zero, no divergence) and writes outputs ONCE. cls2: bad iff
//      end != E (bitwise).  INVARIANT after W: memory of chunk c == outputs
//      of trajectory from g_in[c], for every class.
// R  : warp/batch repair: no-bad fast exit; off-chain silent -> zero-fill +
//      O(1) jump; off-chain active -> dual resim vs g_in-trajectory; exact
//      bitwise chain-return; L1 x-prefetch lookahead.

#define BB 128
#define SS 128
#define HH 128
#define KK 8
#define NCHUNK (BB * SS)          // 16384
#define CPW 16                    // chunks per warp in W
#define WPB 4                     // warps per block in W
#define QJ 16                     // j-steps per smem tile
#define NQ (HH / QJ)              // 8
#define CH_STRIDE 130             // floats; even (STS.64) + 16-lane conflict-free
#define MARGIN 0.01f

__device__ float g_E[NCHUNK];          // spec end state
__device__ float g_S[NCHUNK];          // chunk sum (per-j jumps)
__device__ float g_M[NCHUNK];          // exact linear-trajectory spike bound
__device__ float g_in[NCHUNK];         // B1 state entering chunk
__device__ float g_endv[NCHUNK];       // W: actual end when bad
__device__ unsigned char g_cls[NCHUNK];
__device__ unsigned char g_bad[NCHUNK];

// ---------------------------------------------------------------- kernel Mt
__global__ __launch_bounds__(256) void lif_meta_kernel(
    const float* __restrict__ x, const float* __restrict__ th)
{
    int chunk = blockIdx.x * 256 + threadIdx.x;
    if (chunk >= NCHUNK) return;

    float t[KK];
#pragma unroll
    for (int k = 0; k < KK; ++k) t[k] = __ldg(th + k);

    const float4* __restrict__ xr4 =
        reinterpret_cast<const float4*>(x + (size_t)chunk * HH);

    float s = 0.0f;
    float p = 0.0f;                  // per-j jumped prefix
    float Mp = -CUDART_INF_F;        // exact: max_j (p_j + c(x_j))

    for (int g = 0; g < HH / 4; ++g) {
        float4 xv = xr4[g];
        float xa[4] = {xv.x, xv.y, xv.z, xv.w};
#pragma unroll
        for (int jj = 0; jj < 4; ++jj) {
            float xx = xa[jj];
            // exact per-j spike reach: c = max_m(m*x - th[m-1])
            float c = fmaf(1.0f, xx, -t[0]);
#pragma unroll
            for (int k = 1; k < KK; ++k)
                c = fmaxf(c, fmaf((float)(k + 1), xx, -t[k]));
            Mp = fmaxf(Mp, p + c);
            p += 8.0f * xx;
#pragma unroll
            for (int k = 0; k < KK; ++k) {
                s += xx;
                bool sp = s > t[k];
                s = sp ? 0.0f : s;
            }
        }
    }
    g_E[chunk] = s;
    g_S[chunk] = p;
    g_M[chunk] = Mp;
}

// ---------------------------------------------------------------- kernel B1
__global__ __launch_bounds__(32) void lif_state_kernel()
{
    __shared__ float smM[SS], smS[SS], smE[SS];
    const int b = blockIdx.x, lane = threadIdx.x, base = b * SS;

#pragma unroll
    for (int r = 0; r < SS / 32; ++r) {
        int i = r * 32 + lane;
        smM[i] = g_M[base + i];
        smS[i] = g_S[base + i];
        smE[i] = g_E[base + i];
    }
    __syncwarp();
    if (lane != 0) return;

    float s = 0.0f;
    for (int i = 0; i < SS; ++i) {
        int c = base + i;
        g_in[c] = s;
        g_bad[c] = 0;
        if (s == 0.0f)                      { g_cls[c] = 0; s = smE[i]; }
        else if (s <= -(smM[i] + MARGIN))   { g_cls[c] = 1; s += smS[i]; }
        else                                { g_cls[c] = 2; s = smE[i]; }  // assume merge
    }
}

// ---------------------------------------------------------------- kernel W
__global__ __launch_bounds__(128) void lif_write_kernel(
    const float* __restrict__ x, const float* __restrict__ th,
    float* __restrict__ outs, float* __restrict__ spikes, int write_spikes)
{
    __shared__ float buf[WPB][CPW * CH_STRIDE];   // 4*2080*4 = 33.3 KB

    const int w    = threadIdx.x >> 5;
    const int lane = threadIdx.x & 31;
    const int gw   = blockIdx.x * WPB + w;
    const int chunk0 = gw * CPW;

    float t[KK];
#pragma unroll
    for (int k = 0; k < KK; ++k) t[k] = __ldg(th + k);

    const bool active = lane < CPW;
    const int cl = active ? lane : 0;
    const int mychunk = chunk0 + cl;
    const float* __restrict__ xr = x + (size_t)mychunk * HH;
    float* bp = &buf[w][cl * CH_STRIDE];

    unsigned char cls = g_cls[mychunk];
    // cls1 sentinel: deeply negative state -> all outputs zero, no divergence
    float s = (cls == 1) ? -1e30f : g_in[mychunk];

    for (int q = 0; q < NQ; ++q) {
        if (active) {
#pragma unroll
            for (int g = 0; g < QJ / 4; ++g) {
                float4 xv = *reinterpret_cast<const float4*>(xr + q * QJ + g * 4);
                float xa[4] = {xv.x, xv.y, xv.z, xv.w};
                float o0[KK], o1[KK];
#pragma unroll
                for (int pr = 0; pr < 2; ++pr) {          // j-pairs
#pragma unroll
                    for (int jj = 0; jj < 2; ++jj) {
                        float xx = xa[pr * 2 + jj];
                        float* ob = jj ? o1 : o0;
#pragma unroll
                        for (int k = 0; k < KK; ++k) {
                            s += xx;
                            bool sp = s > t[k];
                            ob[k] = sp ? s : 0.0f;
                            s = sp ? 0.0f : s;
                        }
                    }
                    int j0 = q * QJ + 0;  (void)j0;
                    int jp = g * 4 + pr * 2;              // even, within tile
#pragma unroll
                    for (int k = 0; k < KK; ++k) {
                        float2 v2 = make_float2(o0[k], o1[k]);
                        *reinterpret_cast<float2*>(bp + k * QJ + jp) = v2;  // STS.64
                    }
                }
            }
        }
        __syncwarp();
        {
            int jf = lane & 15;
            int ch = lane >> 4;                      // 0..1
#pragma unroll
            for (int cp = 0; cp < CPW / 2; ++cp) {
                int c = cp * 2 + ch;
                size_t gbase = (size_t)(chunk0 + c) * (KK * HH) + q * QJ + jf;
                const float* sbf = &buf[w][c * CH_STRIDE + jf];
#pragma unroll
                for (int k = 0; k < KK; ++k) {
                    float v = sbf[k * QJ];
                    outs[gbase + k * HH] = v;
                    if (write_spikes)
                        spikes[gbase + k * HH] = v > 0.0f ? 1.0f : 0.0f;
                }
            }
        }
        __syncwarp();
    }

    // chain verification: cls2 chunks must land exactly on E (merge or luck)
    if (active && cls == 2) {
        if (s != g_E[mychunk]) { g_endv[mychunk] = s; g_bad[mychunk] = 1; }
    }
}

// --------------------------------------------------------- shared dual resim
// Resim trajectory-b (start sb) vs trajectory-a (start sa == chunk memory).
// Diff-patch; after a co-spike both trajectories are bitwise-identical, so
// all further writes are no-ops — merge check once per 32 substeps is exact.
// Returns true if merged; otherwise *end_out = final sb.
__device__ __forceinline__ bool dual_patch(
    const float* __restrict__ xrow, const float* __restrict__ t,
    float sa, float sb, float* __restrict__ orow, float* __restrict__ srow,
    int write_spikes, float* end_out)
{
    const float4* __restrict__ xr4 = reinterpret_cast<const float4*>(xrow);
    float4 cur = xr4[0];
    for (int g = 0; g < HH / 4; ++g) {
        float4 nxt = (g + 1 < HH / 4) ? xr4[g + 1] : cur;
        float xa[4] = {cur.x, cur.y, cur.z, cur.w};
        bool co = false;
#pragma unroll
        for (int jj = 0; jj < 4; ++jj) {
            float xx = xa[jj];
            int j = g * 4 + jj;
#pragma unroll
            for (int k = 0; k < KK; ++k) {
                sa += xx; sb += xx;
                bool spa = sa > t[k];
                bool spb = sb > t[k];
                co = co || (spa && spb);
                int idx = k * HH + j;
                float ot = spb ? sb : 0.0f;
                float os = spa ? sa : 0.0f;
                if (ot != os) orow[idx] = ot;
                if (write_spikes && (spa != spb)) srow[idx] = spb ? 1.0f : 0.0f;
                sa = spa ? 0.0f : sa;
                sb = spb ? 0.0f : sb;
            }
        }
        if (co) return true;
        cur = nxt;
    }
    *end_out = sb;
    return false;
}

// ---------------------------------------------------------------- kernel R
__global__ __launch_bounds__(32) void lif_repair_kernel(
    const float* __restrict__ x, const float* __restrict__ th,
    float* __restrict__ outs, float* __restrict__ spikes, int write_spikes)
{
    __shared__ float smIn[SS], smE[SS], smS[SS], smM[SS], smEndv[SS];
    __shared__ unsigned char smBad[SS], smCls[SS];

    const int b = blockIdx.x, lane = threadIdx.x, base = b * SS;

    // fast no-bad exit (4 flag bytes per lane)
    unsigned int word = reinterpret_cast<const unsigned int*>(g_bad + base)[lane];
    unsigned int ballot = __ballot_sync(0xFFFFFFFFu, word != 0u);
    if (!ballot) return;

    // cooperative metadata prefetch
#pragma unroll
    for (int r = 0; r < SS / 32; ++r) {
        int i = r * 32 + lane;
        smIn[i]   = g_in[base + i];
        smE[i]    = g_E[base + i];
        smS[i]    = g_S[base + i];
        smM[i]    = g_M[base + i];
        smEndv[i] = g_endv[base + i];
        smBad[i]  = g_bad[base + i];
        smCls[i]  = g_cls[base + i];
    }
    __syncwarp();

    float t[KK];
#pragma unroll
    for (int k = 0; k < KK; ++k) t[k] = __ldg(th + k);

    // first bad chunk: its s_in (B1 chain) was correct, W output valid.
    int i = 0;
    while (i < SS && !smBad[i]) ++i;
    if (i >= SS) return;
    float s = smEndv[i];
    ++i;

    while (i < SS) {
        // exact bitwise chain-return test
        if (s == smIn[i]) {
            while (i < SS && !smBad[i]) ++i;   // on chain until next bad
            if (i >= SS) return;
            s = smEndv[i];          // its s_in was on-chain -> output valid
            ++i;
            continue;
        }

        // off-chain: prefetch x row two chunks ahead into L1 (hide latency)
        if (i + 2 < SS && lane < 16)
            asm volatile("prefetch.global.L1 [%0];"
                         :: "l"(x + (size_t)(base + i + 2) * HH + lane * 8));

        int c = base + i;
        float* orow = outs + (size_t)c * (KK * HH);
        float* srow = spikes + (size_t)c * (KK * HH);

        if (s <= -(smM[i] + MARGIN)) {
            // truly silent: outputs must be zero
            if (smCls[i] != 1) {     // memory not already zeros
                float4 z = make_float4(0.f, 0.f, 0.f, 0.f);
                float4* o4 = reinterpret_cast<float4*>(orow);
                float4* s4 = reinterpret_cast<float4*>(srow);
#pragma unroll
                for (int it = 0; it < (KK * HH / 4) / 32; ++it) {
                    o4[it * 32 + lane] = z;
                    if (write_spikes) s4[it * 32 + lane] = z;
                }
            }
            s += smS[i];
            ++i;
            continue;
        }

        // active off-chain: memory holds the g_in-trajectory (invariant).
        float endv;
        bool merged = dual_patch(x + (size_t)c * HH, t, smIn[i], s,
                                 orow, srow, write_spikes, &endv);
        if (merged) {
            // identical to the g_in-trajectory afterward -> its exact end:
            s = smBad[i] ? smEndv[i] : smE[i];
        } else {
            s = endv;
        }
        ++i;
    }
}

extern "C" void kernel_launch(void* const* d_in, const int* in_sizes, int n_in,
                              void* d_out, int out_size) {
    const float* x  = (const float*)d_in[0];   // (B, S, H) f32
    const float* th = (const float*)d_in[1];   // (K,) f32
    float* outs = (float*)d_out;

    const long long N = (long long)BB * SS * KK * HH;   // 16777216
    int write_spikes = ((long long)out_size >= 2 * N) ? 1 : 0;
    float* spikes = outs + N;

    lif_meta_kernel<<<NCHUNK / 256, 256>>>(x, th);
    lif_state_kernel<<<BB, 32>>>();
    lif_write_kernel<<<NCHUNK / (CPW * WPB), WPB * 32>>>(x, th, outs, spikes,
                                                         write_spikes);
    lif_repair_kernel<<<BB, 32>>>(x, th, outs, spikes, write_spikes);
}

// round 16
// speedup vs baseline: 2.0785x; 1.0876x over previous
#include <cuda_runtime.h>
#include <math_constants.h>

// LIF_13984413516471  — B=128, S=128, H=128, K=8.
// s += x; spike = s > th[k]; out = spike ? s : 0; s -= out — serial (i,j,k).
// Output: outs[b][i][k][j], spikes[b][i][k][j].
//
// K1 (block/batch, 128 thr): per-chunk metadata sim (spec end E, sum S,
//     EXACT silence bound M) into smem+global; then thread 0 runs the O(1)
//     chain walk: cls0 s==0 exact; cls1 silent jump; cls2 assume merge.
// K2 (block/batch, 256 thr, dyn smem): 8 warps x 16 chunks write the FULL
//     output once, each lane simming ONE trajectory from g_in[c] (cls1 ->
//     sentinel -1e30 => zeros). cls2 bad iff end != E (bitwise), flags in
//     smem. Then warp 0 repairs THIS batch in-kernel (overlapped across
//     blocks): off-chain silent -> zero-fill + O(1) jump; off-chain active
//     -> dual resim vs the g_in-trajectory (memory invariant) with
//     group-granular co-spike exit; exact bitwise chain-return.

#define BB 128
#define SS 128
#define HH 128
#define KK 8
#define NCHUNK (BB * SS)          // 16384
#define CPW 16                    // chunks per warp in K2
#define WPB 8                     // warps per block in K2 (8*16 = 128 = SS)
#define QJ 16                     // j-steps per smem tile
#define NQ (HH / QJ)              // 8
#define CH_STRIDE 130             // floats; even (STS.64) + 16-lane conflict-free
#define MARGIN 0.01f

#define BUF_FLOATS (WPB * CPW * CH_STRIDE)           // 16640
#define K2_SMEM_FLOATS (BUF_FLOATS + 5 * SS + SS/2)  // buf + 5 arrays + 2 byte arrays
#define K2_SMEM_BYTES (K2_SMEM_FLOATS * 4)

__device__ float g_E[NCHUNK];          // spec end state
__device__ float g_S[NCHUNK];          // chunk sum (per-j jumps)
__device__ float g_M[NCHUNK];          // exact linear-trajectory spike bound
__device__ float g_in[NCHUNK];         // chain state entering chunk
__device__ unsigned char g_cls[NCHUNK];

// ---------------------------------------------------------------- kernel K1
__global__ __launch_bounds__(SS) void lif_meta_state_kernel(
    const float* __restrict__ x, const float* __restrict__ th)
{
    __shared__ float smE[SS], smS[SS], smM[SS];

    const int b = blockIdx.x;
    const int i = threadIdx.x;
    const int c = b * SS + i;

    float t[KK];
#pragma unroll
    for (int k = 0; k < KK; ++k) t[k] = __ldg(th + k);

    const float4* __restrict__ xr4 =
        reinterpret_cast<const float4*>(x + (size_t)c * HH);

    float s = 0.0f;
    float p = 0.0f;                  // per-j jumped prefix
    float Mp = -CUDART_INF_F;        // exact: max_j (p_j + c(x_j))

    for (int g = 0; g < HH / 4; ++g) {
        float4 xv = xr4[g];
        float xa[4] = {xv.x, xv.y, xv.z, xv.w};
#pragma unroll
        for (int jj = 0; jj < 4; ++jj) {
            float xx = xa[jj];
            // exact per-j spike reach: cmx = max_m(m*x - th[m-1])
            float cmx = fmaf(1.0f, xx, -t[0]);
#pragma unroll
            for (int k = 1; k < KK; ++k)
                cmx = fmaxf(cmx, fmaf((float)(k + 1), xx, -t[k]));
            Mp = fmaxf(Mp, p + cmx);
            p += 8.0f * xx;
#pragma unroll
            for (int k = 0; k < KK; ++k) {
                s += xx;
                bool sp = s > t[k];
                s = sp ? 0.0f : s;
            }
        }
    }
    smE[i] = s; smS[i] = p; smM[i] = Mp;
    g_E[c] = s; g_S[c] = p; g_M[c] = Mp;
    __syncthreads();

    if (i == 0) {
        float st = 0.0f;
        for (int j = 0; j < SS; ++j) {
            int cc = b * SS + j;
            g_in[cc] = st;
            if (st == 0.0f)                     { g_cls[cc] = 0; st = smE[j]; }
            else if (st <= -(smM[j] + MARGIN))  { g_cls[cc] = 1; st += smS[j]; }
            else                                { g_cls[cc] = 2; st = smE[j]; }
        }
    }
}

// --------------------------------------------------------- shared dual resim
// Resim trajectory-b (start sb) vs trajectory-a (start sa == chunk memory).
// Diff-patch; after a co-spike both are bitwise-identical -> later writes are
// no-ops, so the merge check once per 32 substeps is exact.
__device__ __forceinline__ bool dual_patch(
    const float* __restrict__ xrow, const float* __restrict__ t,
    float sa, float sb, float* __restrict__ orow, float* __restrict__ srow,
    int write_spikes, float* end_out)
{
    const float4* __restrict__ xr4 = reinterpret_cast<const float4*>(xrow);
    float4 cur = xr4[0];
    for (int g = 0; g < HH / 4; ++g) {
        float4 nxt = (g + 1 < HH / 4) ? xr4[g + 1] : cur;
        float xa[4] = {cur.x, cur.y, cur.z, cur.w};
        bool co = false;
#pragma unroll
        for (int jj = 0; jj < 4; ++jj) {
            float xx = xa[jj];
            int j = g * 4 + jj;
#pragma unroll
            for (int k = 0; k < KK; ++k) {
                sa += xx; sb += xx;
                bool spa = sa > t[k];
                bool spb = sb > t[k];
                co = co || (spa && spb);
                int idx = k * HH + j;
                float ot = spb ? sb : 0.0f;
                float os = spa ? sa : 0.0f;
                if (ot != os) orow[idx] = ot;
                if (write_spikes && (spa != spb)) srow[idx] = spb ? 1.0f : 0.0f;
                sa = spa ? 0.0f : sa;
                sb = spb ? 0.0f : sb;
            }
        }
        if (co) return true;
        cur = nxt;
    }
    *end_out = sb;
    return false;
}

// ---------------------------------------------------------------- kernel K2
__global__ __launch_bounds__(WPB * 32) void lif_write_repair_kernel(
    const float* __restrict__ x, const float* __restrict__ th,
    float* __restrict__ outs, float* __restrict__ spikes, int write_spikes)
{
    extern __shared__ float dyn[];
    float* buf    = dyn;                       // BUF_FLOATS
    float* smIn   = dyn + BUF_FLOATS;          // SS
    float* smE    = smIn + SS;
    float* smS    = smE + SS;
    float* smM    = smS + SS;
    float* smEndv = smM + SS;
    unsigned char* smBad = (unsigned char*)(smEndv + SS);   // SS bytes
    unsigned char* smCls = smBad + SS;                      // SS bytes

    const int b    = blockIdx.x;
    const int base = b * SS;
    const int tid  = threadIdx.x;
    const int w    = tid >> 5;
    const int lane = tid & 31;

    // cooperative metadata load (batch-local)
    if (tid < SS) {
        smIn[tid]  = g_in[base + tid];
        smE[tid]   = g_E[base + tid];
        smS[tid]   = g_S[base + tid];
        smM[tid]   = g_M[base + tid];
        smBad[tid] = 0;
        smCls[tid] = g_cls[base + tid];
    }
    __syncthreads();

    float t[KK];
#pragma unroll
    for (int k = 0; k < KK; ++k) t[k] = __ldg(th + k);

    // ---------- W phase: write whole output once ----------
    const bool active = lane < CPW;
    const int cl = active ? lane : 0;
    const int li = w * CPW + cl;               // batch-local chunk 0..127
    const float* __restrict__ xr = x + (size_t)(base + li) * HH;
    float* bp = buf + li * CH_STRIDE;

    unsigned char cls = smCls[li];
    float s = (cls == 1) ? -1e30f : smIn[li];  // cls1 sentinel -> all zeros

    for (int q = 0; q < NQ; ++q) {
        if (active) {
#pragma unroll
            for (int g = 0; g < QJ / 4; ++g) {
                float4 xv = *reinterpret_cast<const float4*>(xr + q * QJ + g * 4);
                float xa[4] = {xv.x, xv.y, xv.z, xv.w};
                float o0[KK], o1[KK];
#pragma unroll
                for (int pr = 0; pr < 2; ++pr) {          // j-pairs
#pragma unroll
                    for (int jj = 0; jj < 2; ++jj) {
                        float xx = xa[pr * 2 + jj];
                        float* ob = jj ? o1 : o0;
#pragma unroll
                        for (int k = 0; k < KK; ++k) {
                            s += xx;
                            bool sp = s > t[k];
                            ob[k] = sp ? s : 0.0f;
                            s = sp ? 0.0f : s;
                        }
                    }
                    int jp = g * 4 + pr * 2;              // even, within tile
#pragma unroll
                    for (int k = 0; k < KK; ++k) {
                        float2 v2 = make_float2(o0[k], o1[k]);
                        *reinterpret_cast<float2*>(bp + k * QJ + jp) = v2;  // STS.64
                    }
                }
            }
        }
        __syncwarp();
        {
            int jf = lane & 15;
            int ch = lane >> 4;                      // 0..1
#pragma unroll
            for (int cp = 0; cp < CPW / 2; ++cp) {
                int c = cp * 2 + ch;
                int lc = w * CPW + c;
                size_t gbase = (size_t)(base + lc) * (KK * HH) + q * QJ + jf;
                const float* sbf = buf + lc * CH_STRIDE + jf;
#pragma unroll
                for (int k = 0; k < KK; ++k) {
                    float v = sbf[k * QJ];
                    outs[gbase + k * HH] = v;
                    if (write_spikes)
                        spikes[gbase + k * HH] = v > 0.0f ? 1.0f : 0.0f;
                }
            }
        }
        __syncwarp();
    }

    // chain verification: cls2 chunks must land exactly on E
    if (active && cls == 2 && s != smE[li]) { smEndv[li] = s; smBad[li] = 1; }
    __syncthreads();

    // ---------- R phase: warp 0 repairs this batch ----------
    if (w != 0) return;

    unsigned int wd = reinterpret_cast<const unsigned int*>(smBad)[lane];
    unsigned int ballot = __ballot_sync(0xFFFFFFFFu, wd != 0u);
    if (!ballot) return;

    // first bad chunk: its s_in (chain) was correct, W output valid.
    int i = 0;
    while (i < SS && !smBad[i]) ++i;
    if (i >= SS) return;
    float rs = smEndv[i];
    ++i;

    while (i < SS) {
        // exact bitwise chain-return test
        if (rs == smIn[i]) {
            while (i < SS && !smBad[i]) ++i;   // on chain until next bad
            if (i >= SS) return;
            rs = smEndv[i];         // its s_in was on-chain -> output valid
            ++i;
            continue;
        }

        // off-chain: prefetch x row two chunks ahead into L1
        if (i + 2 < SS && lane < 16)
            asm volatile("prefetch.global.L1 [%0];"
                         :: "l"(x + (size_t)(base + i + 2) * HH + lane * 8));

        int c = base + i;
        float* orow = outs + (size_t)c * (KK * HH);
        float* srow = spikes + (size_t)c * (KK * HH);

        if (rs <= -(smM[i] + MARGIN)) {
            // truly silent: outputs must be zero
            if (smCls[i] != 1) {     // memory not already zeros
                float4 z = make_float4(0.f, 0.f, 0.f, 0.f);
                float4* o4 = reinterpret_cast<float4*>(orow);
                float4* s4 = reinterpret_cast<float4*>(srow);
#pragma unroll
                for (int it = 0; it < (KK * HH / 4) / 32; ++it) {
                    o4[it * 32 + lane] = z;
                    if (write_spikes) s4[it * 32 + lane] = z;
                }
            }
            rs += smS[i];
            ++i;
            continue;
        }

        // active off-chain: memory holds the g_in-trajectory (invariant).
        float endv;
        bool merged = dual_patch(x + (size_t)c * HH, t, smIn[i], rs,
                                 orow, srow, write_spikes, &endv);
        if (merged) {
            rs = smBad[i] ? smEndv[i] : smE[i];
        } else {
            rs = endv;
        }
        ++i;
    }
}

extern "C" void kernel_launch(void* const* d_in, const int* in_sizes, int n_in,
                              void* d_out, int out_size) {
    const float* x  = (const float*)d_in[0];   // (B, S, H) f32
    const float* th = (const float*)d_in[1];   // (K,) f32
    float* outs = (float*)d_out;

    const long long N = (long long)BB * SS * KK * HH;   // 16777216
    int write_spikes = ((long long)out_size >= 2 * N) ? 1 : 0;
    float* spikes = outs + N;

    cudaFuncSetAttribute(lif_write_repair_kernel,
                         cudaFuncAttributeMaxDynamicSharedMemorySize,
                         K2_SMEM_BYTES);

    lif_meta_state_kernel<<<BB, SS>>>(x, th);
    lif_write_repair_kernel<<<BB, WPB * 32, K2_SMEM_BYTES>>>(
        x, th, outs, spikes, write_spikes);
}